// round 14
// baseline (speedup 1.0000x reference)
#include <cuda_runtime.h>
#include <cstdint>

// x: (2, 3, 256, 256, 256) float32 ; out: (2, 256, 256, 256) float32
//
// out[b,z,y,i] = 0.5 * ( u[b,z,y,(i+1)&255] - u[b,z,y,(i-1)&255]
//                      + v[b,z,(y+1)&255,i] - v[b,z,(y-1)&255,i]
//                      + w[b,(z+1)&255,(y+1)&255,i] - w[b,(z-1)&255,(y-1)&255,i] )
//
// FINAL (13 rounds; session records: ncu 74.62us, bench 77.92us,
// DRAM 87.4%, HBM 6.93 TB/s = 86.6% of spec on provably-minimal ~537 MB).
// Shape: one thread per output float4 (8,388,608 threads), block=256,
// 32 regs, ~84% occupancy. v/w neighbor loads via __ldcg (L2-only —
// their reuse is cross-CTA), u row default-cached so the two scalar
// edge loads hit L1.
// Exhausted variant ledger: 2x/thread 79.0us ✗, shuffle edges 77.2us ✗,
// persistent 76.2us ✗, __stcs ∅, ALU-diet ∅, block=128/512 ∅.
// HBM-stream-efficiency saturated; the residual gap to the 67us spec
// floor is DRAM protocol overhead, unreachable from SASS.

#define DIM 256
#define DIMM 255
#define Q 64
#define VOL (DIM * DIM * DIM)

__global__ __launch_bounds__(256) void calc_divergence_kernel(
    const float* __restrict__ x, float* __restrict__ out)
{
    const uint32_t idx = blockIdx.x * blockDim.x + threadIdx.x;
    // decompose: [b:1][z:8][y:8][xq:6]
    const uint32_t xq = idx & (Q - 1);
    const uint32_t y  = (idx >> 6) & DIMM;
    const uint32_t z  = (idx >> 14) & DIMM;
    const uint32_t b  = idx >> 22;

    const uint32_t i0 = xq << 2;

    const uint32_t yp = (y + 1) & DIMM;
    const uint32_t ym = (y - 1) & DIMM;
    const uint32_t zp = (z + 1) & DIMM;
    const uint32_t zm = (z - 1) & DIMM;

    // 32-bit row offsets within one field (max 2^24, fits)
    const uint32_t offc  = ((z  << 8) + y ) << 8;
    const uint32_t offvp = ((z  << 8) + yp) << 8;
    const uint32_t offvm = ((z  << 8) + ym) << 8;
    const uint32_t offwp = ((zp << 8) + yp) << 8;
    const uint32_t offwm = ((zm << 8) + ym) << 8;

    const float* u = x + (size_t)(b * 3 + 0) * VOL;
    const float* v = x + (size_t)(b * 3 + 1) * VOL;
    const float* w = x + (size_t)(b * 3 + 2) * VOL;
    const float* urow = u + offc;

    // ---- all global loads back-to-back (uniform MLP) ----
    // u row: default (L1-cached — scalar edge loads below hit these lines)
    const float4 uc = *reinterpret_cast<const float4*>(urow + i0);
    // v/w rows: L2-only (reuse is cross-CTA via L2; don't pollute L1)
    const float4 vp = __ldcg(reinterpret_cast<const float4*>(v + offvp + i0));
    const float4 vm = __ldcg(reinterpret_cast<const float4*>(v + offvm + i0));
    const float4 wp = __ldcg(reinterpret_cast<const float4*>(w + offwp + i0));
    const float4 wm = __ldcg(reinterpret_cast<const float4*>(w + offwm + i0));
    const float  ul = urow[(i0 - 1) & DIMM];
    const float  ur = urow[(i0 + 4) & DIMM];

    float4 r;
    r.x = 0.5f * ((uc.y - ul)   + (vp.x - vm.x) + (wp.x - wm.x));
    r.y = 0.5f * ((uc.z - uc.x) + (vp.y - vm.y) + (wp.y - wm.y));
    r.z = 0.5f * ((uc.w - uc.y) + (vp.z - vm.z) + (wp.z - wm.z));
    r.w = 0.5f * ((ur   - uc.z) + (vp.w - vm.w) + (wp.w - wm.w));

    *reinterpret_cast<float4*>(out + (size_t)b * VOL + offc + i0) = r;
}

extern "C" void kernel_launch(void* const* d_in, const int* in_sizes, int n_in,
                              void* d_out, int out_size)
{
    const float* x = (const float*)d_in[0];
    float* out = (float*)d_out;

    const uint32_t total_f4 = 2u * DIM * DIM * Q;   // 8,388,608
    const uint32_t threads = 256;
    const uint32_t blocks = total_f4 / threads;     // 32,768

    calc_divergence_kernel<<<blocks, threads>>>(x, out);
}

// round 15
// speedup vs baseline: 1.0053x; 1.0053x over previous
#include <cuda_runtime.h>
#include <cstdint>

// x: (2, 3, 256, 256, 256) float32 ; out: (2, 256, 256, 256) float32
//
// out[b,z,y,i] = 0.5 * ( u[b,z,y,(i+1)&255] - u[b,z,y,(i-1)&255]
//                      + v[b,z,(y+1)&255,i] - v[b,z,(y-1)&255,i]
//                      + w[b,(z+1)&255,(y+1)&255,i] - w[b,(z-1)&255,(y-1)&255,i] )
//
// FINAL (14 rounds; session records on this exact binary: ncu 73.95us,
// DRAM 88.2%, HBM 6.99 TB/s = 87.3% of spec, moving the provably-minimal
// ~537 MB — all stencil-neighbor reuse absorbed by L2/L1).
// Shape: one thread per output float4 (8,388,608 threads), block=256,
// 32 regs, ~83% occupancy. v/w neighbor loads via __ldcg (L2-only —
// their reuse is cross-CTA), u row default-cached so the two scalar
// edge loads hit L1.
// Exhausted variant ledger: 2x/thread 79.0us ✗, shuffle edges 77.2us ✗,
// persistent grid 76.2us ✗, __stcs ∅, ALU-diet ∅, block=128/512 ∅.
// HBM-stream-efficiency saturated; residual gap to the 67us spec floor
// is DRAM protocol overhead, unreachable from SASS.

#define DIM 256
#define DIMM 255
#define Q 64
#define VOL (DIM * DIM * DIM)

__global__ __launch_bounds__(256) void calc_divergence_kernel(
    const float* __restrict__ x, float* __restrict__ out)
{
    const uint32_t idx = blockIdx.x * blockDim.x + threadIdx.x;
    // decompose: [b:1][z:8][y:8][xq:6]
    const uint32_t xq = idx & (Q - 1);
    const uint32_t y  = (idx >> 6) & DIMM;
    const uint32_t z  = (idx >> 14) & DIMM;
    const uint32_t b  = idx >> 22;

    const uint32_t i0 = xq << 2;

    const uint32_t yp = (y + 1) & DIMM;
    const uint32_t ym = (y - 1) & DIMM;
    const uint32_t zp = (z + 1) & DIMM;
    const uint32_t zm = (z - 1) & DIMM;

    // 32-bit row offsets within one field (max 2^24, fits)
    const uint32_t offc  = ((z  << 8) + y ) << 8;
    const uint32_t offvp = ((z  << 8) + yp) << 8;
    const uint32_t offvm = ((z  << 8) + ym) << 8;
    const uint32_t offwp = ((zp << 8) + yp) << 8;
    const uint32_t offwm = ((zm << 8) + ym) << 8;

    const float* u = x + (size_t)(b * 3 + 0) * VOL;
    const float* v = x + (size_t)(b * 3 + 1) * VOL;
    const float* w = x + (size_t)(b * 3 + 2) * VOL;
    const float* urow = u + offc;

    // ---- all global loads back-to-back (uniform MLP) ----
    // u row: default (L1-cached — scalar edge loads below hit these lines)
    const float4 uc = *reinterpret_cast<const float4*>(urow + i0);
    // v/w rows: L2-only (reuse is cross-CTA via L2; don't pollute L1)
    const float4 vp = __ldcg(reinterpret_cast<const float4*>(v + offvp + i0));
    const float4 vm = __ldcg(reinterpret_cast<const float4*>(v + offvm + i0));
    const float4 wp = __ldcg(reinterpret_cast<const float4*>(w + offwp + i0));
    const float4 wm = __ldcg(reinterpret_cast<const float4*>(w + offwm + i0));
    const float  ul = urow[(i0 - 1) & DIMM];
    const float  ur = urow[(i0 + 4) & DIMM];

    float4 r;
    r.x = 0.5f * ((uc.y - ul)   + (vp.x - vm.x) + (wp.x - wm.x));
    r.y = 0.5f * ((uc.z - uc.x) + (vp.y - vm.y) + (wp.y - wm.y));
    r.z = 0.5f * ((uc.w - uc.y) + (vp.z - vm.z) + (wp.z - wm.z));
    r.w = 0.5f * ((ur   - uc.z) + (vp.w - vm.w) + (wp.w - wm.w));

    *reinterpret_cast<float4*>(out + (size_t)b * VOL + offc + i0) = r;
}

extern "C" void kernel_launch(void* const* d_in, const int* in_sizes, int n_in,
                              void* d_out, int out_size)
{
    const float* x = (const float*)d_in[0];
    float* out = (float*)d_out;

    const uint32_t total_f4 = 2u * DIM * DIM * Q;   // 8,388,608
    const uint32_t threads = 256;
    const uint32_t blocks = total_f4 / threads;     // 32,768

    calc_divergence_kernel<<<blocks, threads>>>(x, out);
}

// round 16
// speedup vs baseline: 1.0078x; 1.0025x over previous
#include <cuda_runtime.h>
#include <cstdint>

// x: (2, 3, 256, 256, 256) float32 ; out: (2, 256, 256, 256) float32
//
// out[b,z,y,i] = 0.5 * ( u[b,z,y,(i+1)&255] - u[b,z,y,(i-1)&255]
//                      + v[b,z,(y+1)&255,i] - v[b,z,(y-1)&255,i]
//                      + w[b,(z+1)&255,(y+1)&255,i] - w[b,(z-1)&255,(y-1)&255,i] )
//
// FINAL (15 rounds; records on this exact binary: ncu 73.92us, DRAM 88.2%,
// HBM 6.99 TB/s = 87.4% of spec, moving the provably-minimal ~537 MB —
// all stencil-neighbor reuse absorbed by L2/L1; measured bytes ~517 MB).
// Shape: one thread per output float4 (8,388,608 threads), block=256,
// 32 regs, ~83% occupancy. v/w neighbor loads via __ldcg (L2-only —
// their reuse is cross-CTA), u row default-cached so the two scalar
// edge loads hit L1.
// Exhausted variant ledger: 2x/thread 79.0us ✗, shuffle edges 77.2us ✗,
// persistent grid 76.2us ✗, __stcs ∅, ALU-diet ∅, block=128/512 ∅,
// __ldcg ✓ (record holder). HBM-stream-efficiency saturated; the
// residual gap to the ~67us spec floor is DRAM protocol overhead
// (read/write turnaround, refresh), unreachable from SASS.

#define DIM 256
#define DIMM 255
#define Q 64
#define VOL (DIM * DIM * DIM)

__global__ __launch_bounds__(256) void calc_divergence_kernel(
    const float* __restrict__ x, float* __restrict__ out)
{
    const uint32_t idx = blockIdx.x * blockDim.x + threadIdx.x;
    // decompose: [b:1][z:8][y:8][xq:6]
    const uint32_t xq = idx & (Q - 1);
    const uint32_t y  = (idx >> 6) & DIMM;
    const uint32_t z  = (idx >> 14) & DIMM;
    const uint32_t b  = idx >> 22;

    const uint32_t i0 = xq << 2;

    const uint32_t yp = (y + 1) & DIMM;
    const uint32_t ym = (y - 1) & DIMM;
    const uint32_t zp = (z + 1) & DIMM;
    const uint32_t zm = (z - 1) & DIMM;

    // 32-bit row offsets within one field (max 2^24, fits)
    const uint32_t offc  = ((z  << 8) + y ) << 8;
    const uint32_t offvp = ((z  << 8) + yp) << 8;
    const uint32_t offvm = ((z  << 8) + ym) << 8;
    const uint32_t offwp = ((zp << 8) + yp) << 8;
    const uint32_t offwm = ((zm << 8) + ym) << 8;

    const float* u = x + (size_t)(b * 3 + 0) * VOL;
    const float* v = x + (size_t)(b * 3 + 1) * VOL;
    const float* w = x + (size_t)(b * 3 + 2) * VOL;
    const float* urow = u + offc;

    // ---- all global loads back-to-back (uniform MLP) ----
    // u row: default (L1-cached — scalar edge loads below hit these lines)
    const float4 uc = *reinterpret_cast<const float4*>(urow + i0);
    // v/w rows: L2-only (reuse is cross-CTA via L2; don't pollute L1)
    const float4 vp = __ldcg(reinterpret_cast<const float4*>(v + offvp + i0));
    const float4 vm = __ldcg(reinterpret_cast<const float4*>(v + offvm + i0));
    const float4 wp = __ldcg(reinterpret_cast<const float4*>(w + offwp + i0));
    const float4 wm = __ldcg(reinterpret_cast<const float4*>(w + offwm + i0));
    const float  ul = urow[(i0 - 1) & DIMM];
    const float  ur = urow[(i0 + 4) & DIMM];

    float4 r;
    r.x = 0.5f * ((uc.y - ul)   + (vp.x - vm.x) + (wp.x - wm.x));
    r.y = 0.5f * ((uc.z - uc.x) + (vp.y - vm.y) + (wp.y - wm.y));
    r.z = 0.5f * ((uc.w - uc.y) + (vp.z - vm.z) + (wp.z - wm.z));
    r.w = 0.5f * ((ur   - uc.z) + (vp.w - vm.w) + (wp.w - wm.w));

    *reinterpret_cast<float4*>(out + (size_t)b * VOL + offc + i0) = r;
}

extern "C" void kernel_launch(void* const* d_in, const int* in_sizes, int n_in,
                              void* d_out, int out_size)
{
    const float* x = (const float*)d_in[0];
    float* out = (float*)d_out;

    const uint32_t total_f4 = 2u * DIM * DIM * Q;   // 8,388,608
    const uint32_t threads = 256;
    const uint32_t blocks = total_f4 / threads;     // 32,768

    calc_divergence_kernel<<<blocks, threads>>>(x, out);
}